// round 16
// baseline (speedup 1.0000x reference)
#include <cuda_runtime.h>

typedef unsigned long long u64;

// ---------- packed f32x2 helpers ----------
__device__ __forceinline__ u64 fma2(u64 a, u64 b, u64 c){
    u64 d; asm("fma.rn.f32x2 %0, %1, %2, %3;" : "=l"(d) : "l"(a), "l"(b), "l"(c)); return d;
}
__device__ __forceinline__ u64 mul2(u64 a, u64 b){
    u64 d; asm("mul.rn.f32x2 %0, %1, %2;" : "=l"(d) : "l"(a), "l"(b)); return d;
}
__device__ __forceinline__ u64 pk2(float lo, float hi){
    u64 d; asm("mov.b64 %0, {%1, %2};" : "=l"(d) : "f"(lo), "f"(hi)); return d;
}
__device__ __forceinline__ void upk2(u64 v, float& lo, float& hi){
    asm("mov.b64 {%0, %1}, %2;" : "=f"(lo), "=f"(hi) : "l"(v));
}
__device__ __forceinline__ u64 dup2(float f){ return pk2(f, f); }

// full leaky_relu(x) = 0.505*x + 0.495*|x| — final h only
__device__ __forceinline__ u64 act_lrelu(u64 v){
    u64 av = v & 0x7FFFFFFF7FFFFFFFULL;
    return fma2(av, 0x3EFD70A43EFD70A4ULL, mul2(v, 0x3F0147AE3F0147AEULL));
}
// hidden lrelu g-form: g(x) = x + (0.495/0.505)|x|; 0.505 folded into next weights
__device__ __forceinline__ u64 act_g(u64 v){
    u64 av = v & 0x7FFFFFFF7FFFFFFFULL;
    return fma2(av, 0x3F7AEE423F7AEE42ULL /*0.98019802*/, v);
}
__device__ __forceinline__ float tanh_ap(float x){
    float r; asm("tanh.approx.f32 %0, %1;" : "=f"(r) : "f"(x)); return r;
}
// hidden sigmoid: pure tanh (affine folded into weights)
__device__ __forceinline__ u64 act_tanh(u64 v){
    float lo, hi; upk2(v, lo, hi);
    return pk2(tanh_ap(lo), tanh_ap(hi));
}
// final sigmoid: near-exact ex2+rcp
__device__ __forceinline__ float fast_sigmoid(float x){
    float e; asm("ex2.approx.f32 %0, %1;" : "=f"(e) : "f"(-1.44269504088896341f * x));
    float r; asm("rcp.approx.f32 %0, %1;" : "=f"(r) : "f"(1.0f + e));
    return r;
}
__device__ __forceinline__ u64 act_sige(u64 v){
    float lo, hi; upk2(v, lo, hi);
    return pk2(fast_sigmoid(lo), fast_sigmoid(hi));
}
// ACT codes: 0 = g-lrelu (hidden h), 1 = tanh (hidden z),
//            2 = exact sigmoid (final z), 3 = full lrelu (final h)
template<int ACT> __device__ __forceinline__ u64 act(u64 v){
    if (ACT == 0) return act_g(v);
    else if (ACT == 1) return act_tanh(v);
    else if (ACT == 2) return act_sige(v);
    else return act_lrelu(v);
}

// scatter one quad into two items' accumulator pairs (ddA/ddB in scope)
#define SC2(qv, A0, A1, B0, B1) \
    A0 = fma2(ddA,(qv).x,A0);  B0 = fma2(ddB,(qv).x,B0); \
    A1 = fma2(ddA,(qv).y,A1);  B1 = fma2(ddB,(qv).y,B1);

// layer-3 step for one accumulator pair, two items
#define L3S2(W3, CAi, CBi, widx, rA, rB) { \
    float la, ha, lb, hb; upk2(CAi, la, ha); upk2(CBi, lb, hb); \
    u64 wl = (W3)[widx], wh = (W3)[(widx)+1]; \
    rA = fma2(dup2(la), wl, rA);  rB = fma2(dup2(lb), wl, rB); \
    rA = fma2(dup2(ha), wh, rA);  rB = fma2(dup2(hb), wh, rB); }

// ---------- solo path (2 items) — prologue h / epilogue z ----------
#define SOLO_ITER { \
    ulonglong2 bw = p1[0]; u64 w1 = ((const u64*)p1)[2]; p1 += 2; \
    u64 axA = act<ACT>(fma2(D1A, w1, fma2(D0A, bw.y, bw.x))); \
    u64 axB = act<ACT>(fma2(D1B, w1, fma2(D0B, bw.y, bw.x))); \
    float f0A, f1A, f0B, f1B; \
    upk2(axA, f0A, f1A); upk2(axB, f0B, f1B); \
    { u64 ddA = dup2(f0A), ddB = dup2(f0B); ulonglong2 q; \
      q = p2[0]; SC2(q, CA0,CA1, CB0,CB1) \
      q = p2[1]; SC2(q, CA2,CA3, CB2,CB3) \
      q = p2[2]; SC2(q, CA4,CA5, CB4,CB5) \
      q = p2[3]; SC2(q, CA6,CA7, CB6,CB7) \
      q = p2[4]; SC2(q, CA8,CA9, CB8,CB9) } \
    { u64 ddA = dup2(f1A), ddB = dup2(f1B); ulonglong2 q; \
      q = p2[5]; SC2(q, CA0,CA1, CB0,CB1) \
      q = p2[6]; SC2(q, CA2,CA3, CB2,CB3) \
      q = p2[7]; SC2(q, CA4,CA5, CB4,CB5) \
      q = p2[8]; SC2(q, CA6,CA7, CB6,CB7) \
      q = p2[9]; SC2(q, CA8,CA9, CB8,CB9) } \
    p2 += 10; }

template<int ACT, int ACTF>
__device__ __forceinline__ void path2(const ulonglong2* __restrict__ W1B,
                                      const ulonglong2* __restrict__ W2B,
                                      const u64* __restrict__ W3B,
                                      u64 inA, u64 inB, u64& outA, u64& outB)
{
    float xa0, xa1, xb0, xb1;
    upk2(inA, xa0, xa1); upk2(inB, xb0, xb1);
    u64 D0A = dup2(xa0), D1A = dup2(xa1);
    u64 D0B = dup2(xb0), D1B = dup2(xb1);

    u64 CA0,CA1,CA2,CA3,CA4,CA5,CA6,CA7,CA8,CA9;
    u64 CB0,CB1,CB2,CB3,CB4,CB5,CB6,CB7,CB8,CB9;
    { ulonglong2 b = W2B[0]; CA0=b.x; CA1=b.y; CB0=b.x; CB1=b.y; }
    { ulonglong2 b = W2B[1]; CA2=b.x; CA3=b.y; CB2=b.x; CB3=b.y; }
    { ulonglong2 b = W2B[2]; CA4=b.x; CA5=b.y; CB4=b.x; CB5=b.y; }
    { ulonglong2 b = W2B[3]; CA6=b.x; CA7=b.y; CB6=b.x; CB7=b.y; }
    { ulonglong2 b = W2B[4]; CA8=b.x; CA9=b.y; CB8=b.x; CB9=b.y; }

    const ulonglong2* p1 = W1B;
    const ulonglong2* p2 = W2B + 5;

    #pragma unroll 4
    for (int p = 0; p < 24; p++){ SOLO_ITER }
    SOLO_ITER

    CA0=act<ACT>(CA0); CA1=act<ACT>(CA1); CA2=act<ACT>(CA2); CA3=act<ACT>(CA3);
    CA4=act<ACT>(CA4); CA5=act<ACT>(CA5); CA6=act<ACT>(CA6); CA7=act<ACT>(CA7);
    CA8=act<ACT>(CA8); CA9=act<ACT>(CA9);
    CB0=act<ACT>(CB0); CB1=act<ACT>(CB1); CB2=act<ACT>(CB2); CB3=act<ACT>(CB3);
    CB4=act<ACT>(CB4); CB5=act<ACT>(CB5); CB6=act<ACT>(CB6); CB7=act<ACT>(CB7);
    CB8=act<ACT>(CB8); CB9=act<ACT>(CB9);

    u64 rA = W3B[0], rB = rA;
    L3S2(W3B, CA0, CB0,  1, rA, rB)
    L3S2(W3B, CA1, CB1,  3, rA, rB)
    L3S2(W3B, CA2, CB2,  5, rA, rB)
    L3S2(W3B, CA3, CB3,  7, rA, rB)
    L3S2(W3B, CA4, CB4,  9, rA, rB)
    L3S2(W3B, CA5, CB5, 11, rA, rB)
    L3S2(W3B, CA6, CB6, 13, rA, rB)
    L3S2(W3B, CA7, CB7, 15, rA, rB)
    L3S2(W3B, CA8, CB8, 17, rA, rB)
    L3S2(W3B, CA9, CB9, 19, rA, rB)

    outA = act<ACTF>(rA);
    outB = act<ACTF>(rB);
}

// ---------- fused step: z_t = zpath(h), h_next = hpath(h) — independent ----------
#define FUSED_ITER { \
    ulonglong2 hbw = ph1[0]; u64 hw1 = ((const u64*)ph1)[2]; ph1 += 2; \
    ulonglong2 zbw = pz1[0]; u64 zw1 = ((const u64*)pz1)[2]; pz1 += 2; \
    u64 hxA = act<0>(fma2(D1A, hw1, fma2(D0A, hbw.y, hbw.x))); \
    u64 hxB = act<0>(fma2(D1B, hw1, fma2(D0B, hbw.y, hbw.x))); \
    u64 zxA = act<1>(fma2(D1A, zw1, fma2(D0A, zbw.y, zbw.x))); \
    u64 zxB = act<1>(fma2(D1B, zw1, fma2(D0B, zbw.y, zbw.x))); \
    float f0A,f1A,f0B,f1B, g0A,g1A,g0B,g1B; \
    upk2(hxA,f0A,f1A); upk2(hxB,f0B,f1B); \
    upk2(zxA,g0A,g1A); upk2(zxB,g0B,g1B); \
    { u64 ddA = dup2(f0A), ddB = dup2(f0B); ulonglong2 q; \
      q = ph2[0]; SC2(q, HA0,HA1, HB0,HB1) \
      q = ph2[1]; SC2(q, HA2,HA3, HB2,HB3) \
      q = ph2[2]; SC2(q, HA4,HA5, HB4,HB5) \
      q = ph2[3]; SC2(q, HA6,HA7, HB6,HB7) \
      q = ph2[4]; SC2(q, HA8,HA9, HB8,HB9) } \
    { u64 ddA = dup2(f1A), ddB = dup2(f1B); ulonglong2 q; \
      q = ph2[5]; SC2(q, HA0,HA1, HB0,HB1) \
      q = ph2[6]; SC2(q, HA2,HA3, HB2,HB3) \
      q = ph2[7]; SC2(q, HA4,HA5, HB4,HB5) \
      q = ph2[8]; SC2(q, HA6,HA7, HB6,HB7) \
      q = ph2[9]; SC2(q, HA8,HA9, HB8,HB9) } \
    ph2 += 10; \
    { u64 ddA = dup2(g0A), ddB = dup2(g0B); ulonglong2 q; \
      q = pz2[0]; SC2(q, ZA0,ZA1, ZB0,ZB1) \
      q = pz2[1]; SC2(q, ZA2,ZA3, ZB2,ZB3) \
      q = pz2[2]; SC2(q, ZA4,ZA5, ZB4,ZB5) \
      q = pz2[3]; SC2(q, ZA6,ZA7, ZB6,ZB7) \
      q = pz2[4]; SC2(q, ZA8,ZA9, ZB8,ZB9) } \
    { u64 ddA = dup2(g1A), ddB = dup2(g1B); ulonglong2 q; \
      q = pz2[5]; SC2(q, ZA0,ZA1, ZB0,ZB1) \
      q = pz2[6]; SC2(q, ZA2,ZA3, ZB2,ZB3) \
      q = pz2[7]; SC2(q, ZA4,ZA5, ZB4,ZB5) \
      q = pz2[8]; SC2(q, ZA6,ZA7, ZB6,ZB7) \
      q = pz2[9]; SC2(q, ZA8,ZA9, ZB8,ZB9) } \
    pz2 += 10; }

__device__ __forceinline__ void fused_step(const ulonglong2* __restrict__ sH1,
                                           const ulonglong2* __restrict__ sH2,
                                           const u64* __restrict__ sH3,
                                           const ulonglong2* __restrict__ sZ1,
                                           const ulonglong2* __restrict__ sZ2,
                                           const u64* __restrict__ sZ3,
                                           u64& hA, u64& hB, u64& zA, u64& zB)
{
    float xa0, xa1, xb0, xb1;
    upk2(hA, xa0, xa1); upk2(hB, xb0, xb1);
    u64 D0A = dup2(xa0), D1A = dup2(xa1);
    u64 D0B = dup2(xb0), D1B = dup2(xb1);

    u64 HA0,HA1,HA2,HA3,HA4,HA5,HA6,HA7,HA8,HA9;
    u64 HB0,HB1,HB2,HB3,HB4,HB5,HB6,HB7,HB8,HB9;
    u64 ZA0,ZA1,ZA2,ZA3,ZA4,ZA5,ZA6,ZA7,ZA8,ZA9;
    u64 ZB0,ZB1,ZB2,ZB3,ZB4,ZB5,ZB6,ZB7,ZB8,ZB9;
    { ulonglong2 b = sH2[0]; HA0=b.x; HA1=b.y; HB0=b.x; HB1=b.y; }
    { ulonglong2 b = sH2[1]; HA2=b.x; HA3=b.y; HB2=b.x; HB3=b.y; }
    { ulonglong2 b = sH2[2]; HA4=b.x; HA5=b.y; HB4=b.x; HB5=b.y; }
    { ulonglong2 b = sH2[3]; HA6=b.x; HA7=b.y; HB6=b.x; HB7=b.y; }
    { ulonglong2 b = sH2[4]; HA8=b.x; HA9=b.y; HB8=b.x; HB9=b.y; }
    { ulonglong2 b = sZ2[0]; ZA0=b.x; ZA1=b.y; ZB0=b.x; ZB1=b.y; }
    { ulonglong2 b = sZ2[1]; ZA2=b.x; ZA3=b.y; ZB2=b.x; ZB3=b.y; }
    { ulonglong2 b = sZ2[2]; ZA4=b.x; ZA5=b.y; ZB4=b.x; ZB5=b.y; }
    { ulonglong2 b = sZ2[3]; ZA6=b.x; ZA7=b.y; ZB6=b.x; ZB7=b.y; }
    { ulonglong2 b = sZ2[4]; ZA8=b.x; ZA9=b.y; ZB8=b.x; ZB9=b.y; }

    const ulonglong2* ph1 = sH1;
    const ulonglong2* ph2 = sH2 + 5;
    const ulonglong2* pz1 = sZ1;
    const ulonglong2* pz2 = sZ2 + 5;

    #pragma unroll 4
    for (int p = 0; p < 24; p++){ FUSED_ITER }
    FUSED_ITER

    // h finalize
    HA0=act<0>(HA0); HA1=act<0>(HA1); HA2=act<0>(HA2); HA3=act<0>(HA3);
    HA4=act<0>(HA4); HA5=act<0>(HA5); HA6=act<0>(HA6); HA7=act<0>(HA7);
    HA8=act<0>(HA8); HA9=act<0>(HA9);
    HB0=act<0>(HB0); HB1=act<0>(HB1); HB2=act<0>(HB2); HB3=act<0>(HB3);
    HB4=act<0>(HB4); HB5=act<0>(HB5); HB6=act<0>(HB6); HB7=act<0>(HB7);
    HB8=act<0>(HB8); HB9=act<0>(HB9);
    // z finalize
    ZA0=act<1>(ZA0); ZA1=act<1>(ZA1); ZA2=act<1>(ZA2); ZA3=act<1>(ZA3);
    ZA4=act<1>(ZA4); ZA5=act<1>(ZA5); ZA6=act<1>(ZA6); ZA7=act<1>(ZA7);
    ZA8=act<1>(ZA8); ZA9=act<1>(ZA9);
    ZB0=act<1>(ZB0); ZB1=act<1>(ZB1); ZB2=act<1>(ZB2); ZB3=act<1>(ZB3);
    ZB4=act<1>(ZB4); ZB5=act<1>(ZB5); ZB6=act<1>(ZB6); ZB7=act<1>(ZB7);
    ZB8=act<1>(ZB8); ZB9=act<1>(ZB9);

    u64 rhA = sH3[0], rhB = rhA;
    u64 rzA = sZ3[0], rzB = rzA;
    L3S2(sH3, HA0, HB0,  1, rhA, rhB)  L3S2(sZ3, ZA0, ZB0,  1, rzA, rzB)
    L3S2(sH3, HA1, HB1,  3, rhA, rhB)  L3S2(sZ3, ZA1, ZB1,  3, rzA, rzB)
    L3S2(sH3, HA2, HB2,  5, rhA, rhB)  L3S2(sZ3, ZA2, ZB2,  5, rzA, rzB)
    L3S2(sH3, HA3, HB3,  7, rhA, rhB)  L3S2(sZ3, ZA3, ZB3,  7, rzA, rzB)
    L3S2(sH3, HA4, HB4,  9, rhA, rhB)  L3S2(sZ3, ZA4, ZB4,  9, rzA, rzB)
    L3S2(sH3, HA5, HB5, 11, rhA, rhB)  L3S2(sZ3, ZA5, ZB5, 11, rzA, rzB)
    L3S2(sH3, HA6, HB6, 13, rhA, rhB)  L3S2(sZ3, ZA6, ZB6, 13, rzA, rzB)
    L3S2(sH3, HA7, HB7, 15, rhA, rhB)  L3S2(sZ3, ZA7, ZB7, 15, rzA, rzB)
    L3S2(sH3, HA8, HB8, 17, rhA, rhB)  L3S2(sZ3, ZA8, ZB8, 17, rzA, rzB)
    L3S2(sH3, HA9, HB9, 19, rhA, rhB)  L3S2(sZ3, ZA9, ZB9, 19, rzA, rzB)

    hA = act<3>(rhA);
    hB = act<3>(rhB);
    zA = act<2>(rzA);
    zB = act<2>(rzB);
}

// ---------- shared fills with weight folding ----------
__device__ void fill_L1(float* dstf, const float* __restrict__ W,
                        const float* __restrict__ Bv, float ws, float bs)
{
    for (int e = threadIdx.x; e < 200; e += blockDim.x){
        int p = e >> 3, k = e & 7;
        float v = 0.0f;
        if      (k < 2) v = bs * Bv[2*p + k];
        else if (k < 4) v = ws * W[      2*p + (k-2)];
        else if (k < 6) v = ws * W[50 +  2*p + (k-4)];
        dstf[e] = v;
    }
}
__device__ void fill_L2(float* dstf, const float* __restrict__ W,
                        const float* __restrict__ Bv, float ws, float bs, float bc)
{
    for (int e = threadIdx.x; e < 1020; e += blockDim.x){
        int blk = e / 20, j = e % 20;
        if (blk == 0){
            float cs = 0.0f;
            if (bc != 0.0f)
                for (int i = 0; i < 50; i++) cs += W[i*20 + j];
            dstf[e] = bs * Bv[j] + bc * cs;
        } else {
            dstf[e] = ws * W[(blk - 1) * 20 + j];
        }
    }
}
__device__ void fill_L3(float* dstf, const float* __restrict__ W,
                        const float* __restrict__ Bv, float ws, float bs, float bc)
{
    for (int e = threadIdx.x; e < 42; e += blockDim.x){
        int blk = e >> 1, j = e & 1;
        if (blk == 0){
            float cs = 0.0f;
            if (bc != 0.0f)
                for (int i = 0; i < 20; i++) cs += W[i*2 + j];
            dstf[e] = bs * Bv[j] + bc * cs;
        } else {
            dstf[e] = ws * W[(blk - 1) * 2 + j];
        }
    }
}

// shared layout (ulonglong2 units): H1@0(50)  H2@50(255)  Z1@305(50)  Z2@355(255)
__global__ void __launch_bounds__(128)
recurrent_kernel(const float2* __restrict__ win,
                 const float* __restrict__ Wh1, const float* __restrict__ bh1,
                 const float* __restrict__ Wh2, const float* __restrict__ bh2,
                 const float* __restrict__ Wh3, const float* __restrict__ bh3,
                 const float* __restrict__ Wz1, const float* __restrict__ bz1,
                 const float* __restrict__ Wz2, const float* __restrict__ bz2,
                 const float* __restrict__ Wz3, const float* __restrict__ bz3,
                 float2* __restrict__ out, int Q)
{
    __shared__ ulonglong2 sQ[610];
    __shared__ u64 sP[44];     // H3 @0 (21), Z3 @22 (21)

    const float S = 0.505f;
    fill_L1((float*)(sQ +   0), Wh1, bh1, 1.0f, 1.0f);
    fill_L2((float*)(sQ +  50), Wh2, bh2, S, 1.0f, 0.0f);
    fill_L3((float*)(sP +   0), Wh3, bh3, S, 1.0f, 0.0f);
    fill_L1((float*)(sQ + 305), Wz1, bz1, 0.5f, 0.5f);
    fill_L2((float*)(sQ + 355), Wz2, bz2, 0.25f, 0.5f, 0.25f);
    fill_L3((float*)(sP +  22), Wz3, bz3, 0.5f, 1.0f, 0.5f);
    __syncthreads();

    int tid = blockIdx.x * blockDim.x + threadIdx.x;
    if (tid >= Q) return;

    const ulonglong2* sH1 = sQ;
    const ulonglong2* sH2 = sQ + 50;
    const ulonglong2* sZ1 = sQ + 305;
    const ulonglong2* sZ2 = sQ + 355;
    const u64* sH3 = sP;
    const u64* sZ3 = sP + 22;

    float2 hinA = win[tid];
    float2 hinB = win[tid + Q];
    u64 hA = pk2(hinA.x, hinA.y);
    u64 hB = pk2(hinB.x, hinB.y);

    float2* opA = out + (size_t)tid * 19;
    float2* opB = out + ((size_t)tid + Q) * 19;

    // prologue: h_1 = hpath(h_0)
    path2<0, 3>(sH1, sH2, sH3, hA, hB, hA, hB);

    // fused mainloop: z_t = zpath(h_{t+1}) and h_{t+2} = hpath(h_{t+1}) overlap
    #pragma unroll 1
    for (int t = 0; t < 18; t++){
        u64 zA, zB;
        fused_step(sH1, sH2, sH3, sZ1, sZ2, sZ3, hA, hB, zA, zB);
        float lo, hi;
        upk2(zA, lo, hi); opA[t] = make_float2(lo, hi);
        upk2(zB, lo, hi); opB[t] = make_float2(lo, hi);
    }

    // epilogue: z_18 = zpath(h_19)
    u64 zA, zB;
    path2<1, 2>(sZ1, sZ2, sZ3, hA, hB, zA, zB);
    float lo, hi;
    upk2(zA, lo, hi); opA[18] = make_float2(lo, hi);
    upk2(zB, lo, hi); opB[18] = make_float2(lo, hi);
}

extern "C" void kernel_launch(void* const* d_in, const int* in_sizes, int n_in,
                              void* d_out, int out_size)
{
    const float* w   = (const float*)d_in[0];
    const float* Wh1 = (const float*)d_in[1];
    const float* bh1 = (const float*)d_in[2];
    const float* Wh2 = (const float*)d_in[3];
    const float* bh2 = (const float*)d_in[4];
    const float* Wh3 = (const float*)d_in[5];
    const float* bh3 = (const float*)d_in[6];
    const float* Wz1 = (const float*)d_in[7];
    const float* bz1 = (const float*)d_in[8];
    const float* Wz2 = (const float*)d_in[9];
    const float* bz2 = (const float*)d_in[10];
    const float* Wz3 = (const float*)d_in[11];
    const float* bz3 = (const float*)d_in[12];

    int B = in_sizes[0] / 2;            // 1048576
    int Q = B / 2;                      // 2 items per thread
    int threads = 128;
    int blocks = (Q + threads - 1) / threads;
    recurrent_kernel<<<blocks, threads>>>((const float2*)w,
                                          Wh1, bh1, Wh2, bh2, Wh3, bh3,
                                          Wz1, bz1, Wz2, bz2, Wz3, bz3,
                                          (float2*)d_out, Q);
}

// round 17
// speedup vs baseline: 1.1283x; 1.1283x over previous
#include <cuda_runtime.h>

typedef unsigned long long u64;

// ---------- packed f32x2 helpers ----------
__device__ __forceinline__ u64 fma2(u64 a, u64 b, u64 c){
    u64 d; asm("fma.rn.f32x2 %0, %1, %2, %3;" : "=l"(d) : "l"(a), "l"(b), "l"(c)); return d;
}
__device__ __forceinline__ u64 mul2(u64 a, u64 b){
    u64 d; asm("mul.rn.f32x2 %0, %1, %2;" : "=l"(d) : "l"(a), "l"(b)); return d;
}
__device__ __forceinline__ u64 pk2(float lo, float hi){
    u64 d; asm("mov.b64 %0, {%1, %2};" : "=l"(d) : "f"(lo), "f"(hi)); return d;
}
__device__ __forceinline__ void upk2(u64 v, float& lo, float& hi){
    asm("mov.b64 {%0, %1}, %2;" : "=f"(lo), "=f"(hi) : "l"(v));
}
__device__ __forceinline__ u64 dup2(float f){ return pk2(f, f); }

// full leaky_relu(x) = 0.505*x + 0.495*|x| (slope 0.01) — used only for final h
__device__ __forceinline__ u64 act_lrelu(u64 v){
    u64 av = v & 0x7FFFFFFF7FFFFFFFULL;
    return fma2(av, 0x3EFD70A43EFD70A4ULL /*0.495*/, mul2(v, 0x3F0147AE3F0147AEULL /*0.505*/));
}
// hidden lrelu in g-form: g(x) = x + (0.495/0.505)*|x|; the 0.505 scale is folded
// into the NEXT layer's weights. 1 fma-pipe op instead of 2.
__device__ __forceinline__ u64 act_g(u64 v){
    u64 av = v & 0x7FFFFFFF7FFFFFFFULL;
    return fma2(av, 0x3F7AEE423F7AEE42ULL /*0.98019802*/, v);
}
__device__ __forceinline__ float tanh_ap(float x){
    float r; asm("tanh.approx.f32 %0, %1;" : "=f"(r) : "f"(x)); return r;
}
// hidden sigmoid: PURE tanh. Input x/2 scale folded into producing layer's W,b;
// output affine 0.5t+0.5 folded into next layer's W,b. 0 fma-pipe ops.
__device__ __forceinline__ u64 act_tanh(u64 v){
    float lo, hi; upk2(v, lo, hi);
    return pk2(tanh_ap(lo), tanh_ap(hi));
}
// final-layer sigmoid: near-exact ex2+rcp
__device__ __forceinline__ float fast_sigmoid(float x){
    float e; asm("ex2.approx.f32 %0, %1;" : "=f"(e) : "f"(-1.44269504088896341f * x));
    float r; asm("rcp.approx.f32 %0, %1;" : "=f"(r) : "f"(1.0f + e));
    return r;
}
__device__ __forceinline__ u64 act_sige(u64 v){
    float lo, hi; upk2(v, lo, hi);
    return pk2(fast_sigmoid(lo), fast_sigmoid(hi));
}
// ACT codes: 0 = g-lrelu (hidden h), 1 = tanh (hidden z),
//            2 = exact sigmoid (final z), 3 = full lrelu (final h)
template<int ACT> __device__ __forceinline__ u64 act(u64 v){
    if (ACT == 0) return act_g(v);
    else if (ACT == 1) return act_tanh(v);
    else if (ACT == 2) return act_sige(v);
    else return act_lrelu(v);
}

// scatter one loaded quad into all three items' accumulator pairs
#define SCAT(qv, a0, a1) \
    CA##a0 = fma2(ddA, (qv).x, CA##a0);  CB##a0 = fma2(ddB, (qv).x, CB##a0);  CC##a0 = fma2(ddC, (qv).x, CC##a0); \
    CA##a1 = fma2(ddA, (qv).y, CA##a1);  CB##a1 = fma2(ddB, (qv).y, CB##a1);  CC##a1 = fma2(ddC, (qv).y, CC##a1);

// layer-3 step for one accumulator pair (rows 2i, 2i+1), three items
#define L3STEP(Ci, wlo_idx) { \
    float loA, hiA, loB, hiB, loC, hiC; \
    upk2(CA##Ci, loA, hiA); upk2(CB##Ci, loB, hiB); upk2(CC##Ci, loC, hiC); \
    u64 wl = W3B[wlo_idx], wh = W3B[(wlo_idx)+1]; \
    resA = fma2(dup2(loA), wl, resA);  resB = fma2(dup2(loB), wl, resB);  resC = fma2(dup2(loC), wl, resC); \
    resA = fma2(dup2(hiA), wh, resA);  resB = fma2(dup2(hiB), wh, resB);  resC = fma2(dup2(hiC), wh, resC); }

// one inner iteration body (layer-1 pair p -> scatter into layer-2 accumulators)
#define ITER_BODY { \
    ulonglong2 bw = p1[0]; \
    u64 w1 = ((const u64*)p1)[2]; \
    p1 += 2; \
    u64 axA = fma2(D0A, bw.y, bw.x); axA = fma2(D1A, w1, axA); axA = act<ACT>(axA); \
    u64 axB = fma2(D0B, bw.y, bw.x); axB = fma2(D1B, w1, axB); axB = act<ACT>(axB); \
    u64 axC = fma2(D0C, bw.y, bw.x); axC = fma2(D1C, w1, axC); axC = act<ACT>(axC); \
    float f0A, f1A, f0B, f1B, f0C, f1C; \
    upk2(axA, f0A, f1A); upk2(axB, f0B, f1B); upk2(axC, f0C, f1C); \
    { \
        u64 ddA = dup2(f0A), ddB = dup2(f0B), ddC = dup2(f0C); \
        ulonglong2 q; \
        q = p2[0]; SCAT(q, 0, 1) \
        q = p2[1]; SCAT(q, 2, 3) \
        q = p2[2]; SCAT(q, 4, 5) \
        q = p2[3]; SCAT(q, 6, 7) \
        q = p2[4]; SCAT(q, 8, 9) \
    } \
    { \
        u64 ddA = dup2(f1A), ddB = dup2(f1B), ddC = dup2(f1C); \
        ulonglong2 q; \
        q = p2[5]; SCAT(q, 0, 1) \
        q = p2[6]; SCAT(q, 2, 3) \
        q = p2[7]; SCAT(q, 4, 5) \
        q = p2[8]; SCAT(q, 6, 7) \
        q = p2[9]; SCAT(q, 8, 9) \
    } \
    p2 += 10; }

// ---------- one full 3-layer path, THREE batch items at once ----------
// W1B: 25 pairs x 2 ulonglong2: [ (bias_pair | w_row0_pair), (w_row1_pair | pad) ]
// W2B: [bias: 5 quads][row r: 5 quads each], r = 0..49   (weights pre-folded)
// W3B: [bias pair][row r pair], r = 0..19   (u64 units, pre-folded)
template<int ACT, int ACTF>
__device__ __forceinline__ void path3(const ulonglong2* __restrict__ W1B,
                                      const ulonglong2* __restrict__ W2B,
                                      const u64* __restrict__ W3B,
                                      u64& hA, u64& hB, u64& hC)
{
    float xa0, xa1, xb0, xb1, xc0, xc1;
    upk2(hA, xa0, xa1); upk2(hB, xb0, xb1); upk2(hC, xc0, xc1);
    u64 D0A = dup2(xa0), D1A = dup2(xa1);
    u64 D0B = dup2(xb0), D1B = dup2(xb1);
    u64 D0C = dup2(xc0), D1C = dup2(xc1);

    u64 CA0, CA1, CA2, CA3, CA4, CA5, CA6, CA7, CA8, CA9;
    u64 CB0, CB1, CB2, CB3, CB4, CB5, CB6, CB7, CB8, CB9;
    u64 CC0, CC1, CC2, CC3, CC4, CC5, CC6, CC7, CC8, CC9;
    { ulonglong2 b = W2B[0]; CA0 = b.x; CA1 = b.y; CB0 = b.x; CB1 = b.y; CC0 = b.x; CC1 = b.y; }
    { ulonglong2 b = W2B[1]; CA2 = b.x; CA3 = b.y; CB2 = b.x; CB3 = b.y; CC2 = b.x; CC3 = b.y; }
    { ulonglong2 b = W2B[2]; CA4 = b.x; CA5 = b.y; CB4 = b.x; CB5 = b.y; CC4 = b.x; CC5 = b.y; }
    { ulonglong2 b = W2B[3]; CA6 = b.x; CA7 = b.y; CB6 = b.x; CB7 = b.y; CC6 = b.x; CC7 = b.y; }
    { ulonglong2 b = W2B[4]; CA8 = b.x; CA9 = b.y; CB8 = b.x; CB9 = b.y; CC8 = b.x; CC9 = b.y; }

    const ulonglong2* p1 = W1B;
    const ulonglong2* p2 = W2B + 5;

    // 24 iterations with a 12-wide scheduling window, then the 25th explicitly.
    #pragma unroll 12
    for (int p = 0; p < 24; p++){
        ITER_BODY
    }
    ITER_BODY

    CA0 = act<ACT>(CA0); CA1 = act<ACT>(CA1); CA2 = act<ACT>(CA2); CA3 = act<ACT>(CA3);
    CA4 = act<ACT>(CA4); CA5 = act<ACT>(CA5); CA6 = act<ACT>(CA6); CA7 = act<ACT>(CA7);
    CA8 = act<ACT>(CA8); CA9 = act<ACT>(CA9);
    CB0 = act<ACT>(CB0); CB1 = act<ACT>(CB1); CB2 = act<ACT>(CB2); CB3 = act<ACT>(CB3);
    CB4 = act<ACT>(CB4); CB5 = act<ACT>(CB5); CB6 = act<ACT>(CB6); CB7 = act<ACT>(CB7);
    CB8 = act<ACT>(CB8); CB9 = act<ACT>(CB9);
    CC0 = act<ACT>(CC0); CC1 = act<ACT>(CC1); CC2 = act<ACT>(CC2); CC3 = act<ACT>(CC3);
    CC4 = act<ACT>(CC4); CC5 = act<ACT>(CC5); CC6 = act<ACT>(CC6); CC7 = act<ACT>(CC7);
    CC8 = act<ACT>(CC8); CC9 = act<ACT>(CC9);

    // layer 3: 20 inputs -> 1 packed output pair, all items
    u64 resA = W3B[0];
    u64 resB = resA;
    u64 resC = resA;
    L3STEP(0,  1)
    L3STEP(1,  3)
    L3STEP(2,  5)
    L3STEP(3,  7)
    L3STEP(4,  9)
    L3STEP(5, 11)
    L3STEP(6, 13)
    L3STEP(7, 15)
    L3STEP(8, 17)
    L3STEP(9, 19)

    hA = act<ACTF>(resA);
    hB = act<ACTF>(resB);
    hC = act<ACTF>(resC);
}

// ---------- shared fills with weight folding (element-wise, no per-thread arrays) ----------
// L1 block: 25 pairs x 8 floats: {b[2p],b[2p+1], W[0][2p],W[0][2p+1], W[1][2p],W[1][2p+1], 0,0}
// all entries scaled: bias*bs, weights*ws
__device__ void fill_L1(float* dstf, const float* __restrict__ W,
                        const float* __restrict__ Bv, float ws, float bs)
{
    for (int e = threadIdx.x; e < 200; e += blockDim.x){
        int p = e >> 3, k = e & 7;
        float v = 0.0f;
        if      (k < 2) v = bs * Bv[2*p + k];
        else if (k < 4) v = ws * W[      2*p + (k-2)];   // row 0 of W[2][50]
        else if (k < 6) v = ws * W[50 +  2*p + (k-4)];   // row 1
        dstf[e] = v;
    }
}
// L2 block (float view): [bias': 20][row r: ws*W], r=0..49
// bias'[j] = bs*b[j] + bc*sum_i W[i][j]
__device__ void fill_L2(float* dstf, const float* __restrict__ W,
                        const float* __restrict__ Bv, float ws, float bs, float bc)
{
    for (int e = threadIdx.x; e < 1020; e += blockDim.x){
        int blk = e / 20, j = e % 20;
        if (blk == 0){
            float cs = 0.0f;
            if (bc != 0.0f)
                for (int i = 0; i < 50; i++) cs += W[i*20 + j];
            dstf[e] = bs * Bv[j] + bc * cs;
        } else {
            dstf[e] = ws * W[(blk - 1) * 20 + j];
        }
    }
}
// L3 block (float view): [b0',b1'][row r: ws*W[2r], ws*W[2r+1]], r=0..19
// bias'[j] = bs*b[j] + bc*sum_i W[i][j]
__device__ void fill_L3(float* dstf, const float* __restrict__ W,
                        const float* __restrict__ Bv, float ws, float bs, float bc)
{
    for (int e = threadIdx.x; e < 42; e += blockDim.x){
        int blk = e >> 1, j = e & 1;
        if (blk == 0){
            float cs = 0.0f;
            if (bc != 0.0f)
                for (int i = 0; i < 20; i++) cs += W[i*2 + j];
            dstf[e] = bs * Bv[j] + bc * cs;
        } else {
            dstf[e] = ws * W[(blk - 1) * 2 + j];
        }
    }
}

// shared layout (ulonglong2 units): H1@0(50)  H2@50(255)  Z1@305(50)  Z2@355(255)
__global__ void __launch_bounds__(128)
recurrent_kernel(const float2* __restrict__ win,
                 const float* __restrict__ Wh1, const float* __restrict__ bh1,
                 const float* __restrict__ Wh2, const float* __restrict__ bh2,
                 const float* __restrict__ Wh3, const float* __restrict__ bh3,
                 const float* __restrict__ Wz1, const float* __restrict__ bz1,
                 const float* __restrict__ Wz2, const float* __restrict__ bz2,
                 const float* __restrict__ Wz3, const float* __restrict__ bz3,
                 float2* __restrict__ out, int Q, int B)
{
    __shared__ ulonglong2 sQ[610];
    __shared__ u64 sP[44];     // H3 @0 (21), Z3 @22 (21)

    const float S = 0.505f;    // lrelu scale folded into next h-layer weights
    fill_L1((float*)(sQ +   0), Wh1, bh1, 1.0f, 1.0f);
    fill_L2((float*)(sQ +  50), Wh2, bh2, S, 1.0f, 0.0f);
    fill_L3((float*)(sP +   0), Wh3, bh3, S, 1.0f, 0.0f);
    fill_L1((float*)(sQ + 305), Wz1, bz1, 0.5f, 0.5f);
    fill_L2((float*)(sQ + 355), Wz2, bz2, 0.25f, 0.5f, 0.25f);
    fill_L3((float*)(sP +  22), Wz3, bz3, 0.5f, 1.0f, 0.5f);
    __syncthreads();

    int tid = blockIdx.x * blockDim.x + threadIdx.x;
    if (tid >= Q) return;

    int idxA = tid;
    int idxB = tid + Q;
    int idxC = tid + 2 * Q;
    bool hasC = (idxC < B);
    int idxCl = hasC ? idxC : (B - 1);

    float2 hinA = win[idxA];
    float2 hinB = win[idxB];
    float2 hinC = win[idxCl];
    u64 hA = pk2(hinA.x, hinA.y);
    u64 hB = pk2(hinB.x, hinB.y);
    u64 hC = pk2(hinC.x, hinC.y);

    float2* opA = out + (size_t)idxA * 19;
    float2* opB = out + (size_t)idxB * 19;
    float2* opC = out + (size_t)idxCl * 19;

    #pragma unroll 1
    for (int t = 0; t < 19; t++){
        // h path: g-lrelu hidden, full lrelu final
        path3<0, 3>(sQ +   0, sQ +  50, sP +  0, hA, hB, hC);
        // z path: tanh hidden (folded), exact sigmoid final
        u64 zA = hA, zB = hB, zC = hC;
        path3<1, 2>(sQ + 305, sQ + 355, sP + 22, zA, zB, zC);
        float lo, hi;
        upk2(zA, lo, hi); opA[t] = make_float2(lo, hi);
        upk2(zB, lo, hi); opB[t] = make_float2(lo, hi);
        if (hasC) { upk2(zC, lo, hi); opC[t] = make_float2(lo, hi); }
    }
}

extern "C" void kernel_launch(void* const* d_in, const int* in_sizes, int n_in,
                              void* d_out, int out_size)
{
    const float* w   = (const float*)d_in[0];
    const float* Wh1 = (const float*)d_in[1];
    const float* bh1 = (const float*)d_in[2];
    const float* Wh2 = (const float*)d_in[3];
    const float* bh2 = (const float*)d_in[4];
    const float* Wh3 = (const float*)d_in[5];
    const float* bh3 = (const float*)d_in[6];
    const float* Wz1 = (const float*)d_in[7];
    const float* bz1 = (const float*)d_in[8];
    const float* Wz2 = (const float*)d_in[9];
    const float* bz2 = (const float*)d_in[10];
    const float* Wz3 = (const float*)d_in[11];
    const float* bz3 = (const float*)d_in[12];

    int B = in_sizes[0] / 2;            // 1048576
    int Q = (B + 2) / 3;
    int threads = 128;
    int blocks = (Q + threads - 1) / threads;
    recurrent_kernel<<<blocks, threads>>>((const float2*)w,
                                          Wh1, bh1, Wh2, bh2, Wh3, bh3,
                                          Wz1, bz1, Wz2, bz2, Wz3, bz3,
                                          (float2*)d_out, Q, B);
}